// round 17
// baseline (speedup 1.0000x reference)
#include <cuda_runtime.h>
#include <math.h>

// ROI max pooling via 2x2 max-pyramid tables + batched warp-uniform loads,
// two i-bins per block (amortized bounds + epilogue).
//
// Pass 1 (fused): NCHW [2,256,38,38] -> four NHWC tables [2,38,38,256]:
//   T00=feat, TP=max{h,h+1}, TQ=max{w,w+1}, TPQ=2x2 max (edge-clamped).
//   Block (0,0,0) also precomputes per-roi bin bounds (packed ints).
//
// Pass 2: grid=(roi, 4): y<3 -> bins i=2y,2y+1; y=3 -> i=6 only.
//   block = (64 c4-lanes, 7 j) = 448 threads; thread = bin x 4 channels.
//   Bin covered by KH x KW pyramid loads (KH,KW<=4, warp-uniform),
//   positions min(start+2k, end-2); n==1 dims use non-paired tables.
//   Each bin's loads issue back-to-back before any consuming max.
//
// Bin math (non-negative ints == Python floor-div):
//   x1=floor(rx1/16),..., rh=y2-y1+1, rw=x2-x1+1
//   hstart_i = y1 + (i*rh)/7, hend_i = y1 + ((i+1)*rh+6)/7  (same for w/j)
// Coords in [0,607.9] => windows inside [0,38), non-empty.

#define N_IMG 2
#define CHN   256
#define C4    (CHN/4)            // 64
#define H_    38
#define W_    38
#define HW    (H_ * W_)
#define NUM_ROIS 256
#define OUT_H 7
#define OUT_W 7
#define BINS  (OUT_H * OUT_W)
#define SPATIAL_SCALE 0.0625f
#define PTHREADS (C4 * OUT_W)    // 448
#define RSTRIDE ((size_t)(W_ * C4))   // row stride in float4 units

__device__ float g_T00[N_IMG * HW * CHN];   // [N][H][W][C]
__device__ float g_TP [N_IMG * HW * CHN];
__device__ float g_TQ [N_IMG * HW * CHN];
__device__ float g_TPQ[N_IMG * HW * CHN];
__device__ int   g_base4[NUM_ROIS];         // b * HW * C4 (float4 units)
__device__ int   g_hb[NUM_ROIS * OUT_H];    // hstart | hend<<8
__device__ int   g_wb[NUM_ROIS * OUT_W];    // wstart | wend<<8

// ---------------------------------------------------------------------------
// Pass 1: transpose + pyramid build + (block 0) bounds precompute.
// ---------------------------------------------------------------------------
__global__ void build_kernel(const float* __restrict__ in,
                             const float* __restrict__ rois)
{
    __shared__ float t00[32][33], tP[32][33], tQ[32][33], tPQ[32][33];
    int n   = blockIdx.z;
    int hw0 = blockIdx.x * 32;
    int c0  = blockIdx.y * 32;

    if (blockIdx.x == 0 && blockIdx.y == 0 && blockIdx.z == 0) {
        int t = threadIdx.y * 32 + threadIdx.x;     // 0..255
        if (t < NUM_ROIS) {
            const float* r = rois + t * 5;
            int b  = (int)r[0];
            int x1 = (int)floorf(r[1] * SPATIAL_SCALE);
            int y1 = (int)floorf(r[2] * SPATIAL_SCALE);
            int x2 = (int)floorf(r[3] * SPATIAL_SCALE);
            int y2 = (int)floorf(r[4] * SPATIAL_SCALE);
            int rh = y2 - y1 + 1;
            int rw = x2 - x1 + 1;
            g_base4[t] = b * HW * C4;
            #pragma unroll
            for (int i = 0; i < OUT_H; ++i) {
                int hs = y1 + (i * rh) / OUT_H;
                int he = y1 + ((i + 1) * rh + OUT_H - 1) / OUT_H;
                g_hb[t * OUT_H + i] = hs | (he << 8);
            }
            #pragma unroll
            for (int j = 0; j < OUT_W; ++j) {
                int ws = x1 + (j * rw) / OUT_W;
                int we = x1 + ((j + 1) * rw + OUT_W - 1) / OUT_W;
                g_wb[t * OUT_W + j] = ws | (we << 8);
            }
        }
    }

    const float* inp = in + (size_t)n * CHN * HW;
    size_t obase = (size_t)n * HW * CHN;

    #pragma unroll
    for (int k = 0; k < 32; k += 8) {
        int c  = c0 + threadIdx.y + k;
        int hw = hw0 + threadIdx.x;
        float v0 = 0.f, vh = 0.f, vw = 0.f, vhw = 0.f;
        if (hw < HW) {
            int h = hw / W_;
            int w = hw - h * W_;
            int dw = (w + 1 < W_) ? 1  : 0;
            int dh = (h + 1 < H_) ? W_ : 0;
            const float* p = inp + (size_t)c * HW + hw;
            v0  = p[0];
            vw  = p[dw];
            vh  = p[dh];
            vhw = p[dh + dw];
        }
        t00[threadIdx.y + k][threadIdx.x] = v0;
        tP [threadIdx.y + k][threadIdx.x] = fmaxf(v0, vh);
        tQ [threadIdx.y + k][threadIdx.x] = fmaxf(v0, vw);
        tPQ[threadIdx.y + k][threadIdx.x] = fmaxf(fmaxf(v0, vh), fmaxf(vw, vhw));
    }
    __syncthreads();
    #pragma unroll
    for (int k = 0; k < 32; k += 8) {
        int hw = hw0 + threadIdx.y + k;
        if (hw < HW) {
            size_t o = obase + (size_t)hw * CHN + c0 + threadIdx.x;
            g_T00[o] = t00[threadIdx.x][threadIdx.y + k];
            g_TP [o] = tP [threadIdx.x][threadIdx.y + k];
            g_TQ [o] = tQ [threadIdx.x][threadIdx.y + k];
            g_TPQ[o] = tPQ[threadIdx.x][threadIdx.y + k];
        }
    }
}

__device__ __forceinline__ float4 max4(float4 a, float4 b)
{
    return make_float4(fmaxf(a.x, b.x), fmaxf(a.y, b.y),
                       fmaxf(a.z, b.z), fmaxf(a.w, b.w));
}

// One bin's pooled max for 4 channels; KW/wp warp-uniform, hb block-uniform.
__device__ __forceinline__ float4 pool_one(int hb, bool wp,
                                           int w0, int w1, int w2, int w3,
                                           int KW, int base_lane)
{
    int hs = hb & 0xff, he = hb >> 8, nh = he - hs;
    bool hp = (nh > 1);
    const float* tabf = hp ? (wp ? g_TPQ : g_TP)
                           : (wp ? g_TQ  : g_T00);
    const float4* tab = (const float4*)tabf + base_lane;
    int hlast = hp ? (he - 2) : hs;
    int KH = (nh + 1) >> 1;               // 1..4

    const float NI = -__int_as_float(0x7f800000);
    float4 m0 = make_float4(NI, NI, NI, NI);
    float4 m1 = m0;
    const float4* r0 = tab + (size_t)hs * RSTRIDE;

    switch (KW) {
    case 1:
        if (KH == 1) {
            m0 = r0[w0];
        } else {
            for (int kh = 0; kh < KH; kh += 2) {
                const float4* ra = tab + (size_t)min(hs + 2*kh,     hlast) * RSTRIDE;
                const float4* rb = tab + (size_t)min(hs + 2*kh + 2, hlast) * RSTRIDE;
                float4 a = ra[w0];
                float4 b = rb[w0];
                m0 = max4(m0, a);
                m1 = max4(m1, b);
            }
        }
        break;
    case 2:
        if (KH == 1) {
            float4 a = r0[w0];
            float4 b = r0[w1];
            m0 = a; m1 = b;
        } else {
            for (int kh = 0; kh < KH; kh += 2) {
                const float4* ra = tab + (size_t)min(hs + 2*kh,     hlast) * RSTRIDE;
                const float4* rb = tab + (size_t)min(hs + 2*kh + 2, hlast) * RSTRIDE;
                float4 a = ra[w0];
                float4 b = ra[w1];
                float4 c = rb[w0];
                float4 d = rb[w1];
                m0 = max4(m0, max4(a, c));
                m1 = max4(m1, max4(b, d));
            }
        }
        break;
    case 3:
        for (int kh = 0; kh < KH; ++kh) {
            const float4* rp = tab + (size_t)min(hs + 2*kh, hlast) * RSTRIDE;
            float4 a = rp[w0];
            float4 b = rp[w1];
            float4 c = rp[w2];
            m0 = max4(m0, max4(a, b));
            m1 = max4(m1, c);
        }
        break;
    default:  // KW == 4
        for (int kh = 0; kh < KH; ++kh) {
            const float4* rp = tab + (size_t)min(hs + 2*kh, hlast) * RSTRIDE;
            float4 a = rp[w0];
            float4 b = rp[w1];
            float4 c = rp[w2];
            float4 d = rp[w3];
            m0 = max4(m0, max4(a, b));
            m1 = max4(m1, max4(c, d));
        }
        break;
    }
    return max4(m0, m1);
}

// ---------------------------------------------------------------------------
// Pass 2: grid = (NUM_ROIS, 4), block = (C4, OUT_W) = (64, 7)
//   y<3: bins i=2y and 2y+1; y=3: bin i=6.
// ---------------------------------------------------------------------------
__global__ void __launch_bounds__(PTHREADS, 4)
roi_pool_pyr2(float* __restrict__ out)
{
    __shared__ float s[2][CHN * OUT_W];   // [bin][c*7 + j]

    int roi  = blockIdx.x;
    int y    = blockIdx.y;
    int iA   = 2 * y;                     // 0,2,4,6
    bool hasB = (y < 3);
    int iB   = hasB ? iA + 1 : iA;

    int lane = threadIdx.x;               // c4 index
    int j    = threadIdx.y;               // warp-uniform

    int wb = g_wb[roi * OUT_W + j];
    int ws = wb & 0xff, we = wb >> 8, nw = we - ws;   // warp-uniform
    bool wp = (nw > 1);
    int wlast = wp ? (we - 2) : ws;
    int KW = (nw + 1) >> 1;               // 1..4

    int w0 = ws * C4;
    int w1 = min(ws + 2, wlast) * C4;
    int w2 = min(ws + 4, wlast) * C4;
    int w3 = min(ws + 6, wlast) * C4;

    int base_lane = g_base4[roi] + lane;
    int hbA = g_hb[roi * OUT_H + iA];
    int hbB = g_hb[roi * OUT_H + iB];

    int c0 = lane * 4;

    // bin A
    {
        float4 m = pool_one(hbA, wp, w0, w1, w2, w3, KW, base_lane);
        s[0][(c0 + 0) * OUT_W + j] = m.x;
        s[0][(c0 + 1) * OUT_W + j] = m.y;
        s[0][(c0 + 2) * OUT_W + j] = m.z;
        s[0][(c0 + 3) * OUT_W + j] = m.w;
    }
    // bin B (registers of A are dead -> reused)
    if (hasB) {
        float4 m = pool_one(hbB, wp, w0, w1, w2, w3, KW, base_lane);
        s[1][(c0 + 0) * OUT_W + j] = m.x;
        s[1][(c0 + 1) * OUT_W + j] = m.y;
        s[1][(c0 + 2) * OUT_W + j] = m.z;
        s[1][(c0 + 3) * OUT_W + j] = m.w;
    }
    __syncthreads();

    // writeout: linear smem reads, one div-by-7 per thread, runs of 7 in gmem
    int tid = threadIdx.y * C4 + threadIdx.x;     // 0..447
    int cq  = tid / OUT_W;
    int jr  = tid - cq * OUT_W;
    float* obA = out + (size_t)roi * CHN * BINS + iA * OUT_W + jr;
    #pragma unroll
    for (int k = 0; k < 4; ++k)
        obA[(size_t)(cq + 64 * k) * BINS] = s[0][tid + k * PTHREADS];
    if (hasB) {
        float* obB = out + (size_t)roi * CHN * BINS + iB * OUT_W + jr;
        #pragma unroll
        for (int k = 0; k < 4; ++k)
            obB[(size_t)(cq + 64 * k) * BINS] = s[1][tid + k * PTHREADS];
    }
}

extern "C" void kernel_launch(void* const* d_in, const int* in_sizes, int n_in,
                              void* d_out, int out_size)
{
    const float* feat = (const float*)d_in[0];
    const float* rois = (const float*)d_in[1];
    float* out = (float*)d_out;

    dim3 tgrid((HW + 31) / 32, CHN / 32, N_IMG);
    dim3 tblock(32, 8);
    build_kernel<<<tgrid, tblock>>>(feat, rois);

    dim3 pgrid(NUM_ROIS, 4);
    dim3 pblock(C4, OUT_W);
    roi_pool_pyr2<<<pgrid, pblock>>>(out);
}